// round 9
// baseline (speedup 1.0000x reference)
#include <cuda_runtime.h>
#include <string.h>

#define D128 128
#define H0 64
#define W0 96
#define HW0 (H0 * W0)   // 6144

// fp32 pyramids (HWD layout). L0 786432, L1 196608, L2 49152, L3 12288.
__device__ __align__(16) float g_f1[1044480];
__device__ __align__(16) float g_f2[1044480];

typedef unsigned long long ull;

__device__ __forceinline__ void fma2(ull& d, ull a, ull b) {
    asm("fma.rn.f32x2 %0, %1, %2, %3;" : "=l"(d) : "l"(a), "l"(b), "l"(d));
}
__device__ __forceinline__ ull pack2(float x, float y) {
    ull r; asm("mov.b64 %0, {%1, %2};" : "=l"(r) : "f"(x), "f"(y)); return r;
}

// ---------------------------------------------------------------------------
// Kernel 1: fused transpose + full pyramid build. One block per 8x8 pixel
// tile per map, 512 threads. grid (96,1,2).
// ---------------------------------------------------------------------------
__global__ __launch_bounds__(512) void build_kernel(const float* __restrict__ f1,
                                                    const float* __restrict__ f2) {
    __shared__ float s0[8][8][128];   // 32KB
    __shared__ float s1[4][4][128];   // 8KB
    __shared__ float s2[2][2][128];   // 2KB
    int map = blockIdx.z;
    const float* in = map ? f2 : f1;
    float* base = map ? g_f2 : g_f1;
    int tx0 = (blockIdx.x % 12) * 8;
    int ty0 = (blockIdx.x / 12) * 8;
    int t = threadIdx.x;

    {
        int d = t >> 2;
        int sl = t & 3;
        const float* src = in + d * HW0 + ty0 * W0 + tx0;
        float4 v00 = *(const float4*)(src + (2 * sl) * W0);
        float4 v01 = *(const float4*)(src + (2 * sl) * W0 + 4);
        float4 v10 = *(const float4*)(src + (2 * sl + 1) * W0);
        float4 v11 = *(const float4*)(src + (2 * sl + 1) * W0 + 4);
        int y0 = 2 * sl, y1 = 2 * sl + 1;
        s0[y0][0][d] = v00.x; s0[y0][1][d] = v00.y; s0[y0][2][d] = v00.z; s0[y0][3][d] = v00.w;
        s0[y0][4][d] = v01.x; s0[y0][5][d] = v01.y; s0[y0][6][d] = v01.z; s0[y0][7][d] = v01.w;
        s0[y1][0][d] = v10.x; s0[y1][1][d] = v10.y; s0[y1][2][d] = v10.z; s0[y1][3][d] = v10.w;
        s0[y1][4][d] = v11.x; s0[y1][5][d] = v11.y; s0[y1][6][d] = v11.z; s0[y1][7][d] = v11.w;
    }
    __syncthreads();

#pragma unroll
    for (int i = 0; i < 4; i++) {
        int idx = i * 512 + t;
        int c4 = idx & 31;
        int px = idx >> 5;
        int y = px >> 3, x = px & 7;
        float4 w = *(float4*)&s0[y][x][c4 * 4];
        int gp = (ty0 + y) * W0 + tx0 + x;
        *(float4*)(base + gp * D128 + c4 * 4) = w;
    }

#pragma unroll
    for (int i = 0; i < 4; i++) {
        int idx = i * 512 + t;
        int c = idx & 127;
        int px = idx >> 7;
        int y = px >> 2, x = px & 3;
        float r = 0.25f * (s0[2*y][2*x][c] + s0[2*y][2*x+1][c]
                         + s0[2*y+1][2*x][c] + s0[2*y+1][2*x+1][c]);
        s1[y][x][c] = r;
        int gp = (ty0 / 2 + y) * 48 + tx0 / 2 + x;
        base[786432 + gp * D128 + c] = r;
    }
    __syncthreads();

    {
        int c = t & 127;
        int px = t >> 7;
        int y = px >> 1, x = px & 1;
        float r = 0.25f * (s1[2*y][2*x][c] + s1[2*y][2*x+1][c]
                         + s1[2*y+1][2*x][c] + s1[2*y+1][2*x+1][c]);
        s2[y][x][c] = r;
        int gp = (ty0 / 4 + y) * 24 + tx0 / 4 + x;
        base[983040 + gp * D128 + c] = r;
    }
    __syncthreads();

    if (t < 128) {
        float r = 0.25f * (s2[0][0][t] + s2[0][1][t] + s2[1][0][t] + s2[1][1][t]);
        int gp = (ty0 / 8) * 12 + tx0 / 8;
        base[1032192 + gp * D128 + t] = r;
    }
}

// ---------------------------------------------------------------------------
// Kernel 2: fused correlation lookup. 256 threads per pixel PAIR.
// Dot phase: ONE warp per position, 4x LDG.32 with lanes spanning one full
// 128B line each (cross-LDG 1.0 cyc/wf path, no within-LDG replays).
// Warps 0-3 -> side 0, warps 4-7 -> side 1; 25 passes each.
// ---------------------------------------------------------------------------
__global__ __launch_bounds__(256, 6) void corr_kernel(const float* __restrict__ coords,
                                                      float* __restrict__ out) {
    int gq = (blockIdx.x % 148) * 28 + blockIdx.x / 148;
    if (gq >= 4080) return;

    int lvl, q;
    if (gq < 3072)      { lvl = 0; q = gq; }
    else if (gq < 3840) { lvl = 1; q = gq - 3072; }
    else if (gq < 4032) { lvl = 2; q = gq - 3840; }
    else                { lvl = 3; q = gq - 4032; }

    int loff, ooff;
    switch (lvl) {
        case 0:  loff = 0;       ooff = 0;      break;
        case 1:  loff = 786432;  ooff = 497664; break;
        case 2:  loff = 983040;  ooff = 622080; break;
        default: loff = 1032192; ooff = 653184; break;
    }
    const int Hl = H0 >> lvl, Wl = W0 >> lvl;

    int t    = threadIdx.x;
    int side = t >> 7;          // for coords/addr phases
    int tt   = t & 127;
    int p    = 2 * q + side;
    int py = p / Wl, px = p - py * Wl;

    __shared__ float sh_c[2][2];
    __shared__ int   sh_addr[2][128];
    __shared__ float sh_dot[2][112];

    int w    = t >> 5;          // warp 0..7
    int lane = t & 31;

    // --- coords at this level (jax.image.resize linear antialias semantics)
    if (tt < 2) {
        float c;
        if (lvl == 0) {
            c = coords[tt * HW0 + p];
        } else {
            int   f    = 1 << lvl;
            float invf = 1.0f / (float)f;
            float sy = ((float)py + 0.5f) * (float)f - 0.5f;
            float sx = ((float)px + 0.5f) * (float)f - 0.5f;
            int jylo = max(0,      (int)floorf(sy - (float)f) + 1);
            int jyhi = min(H0 - 1, (int)floorf(sy + (float)f));
            int jxlo = max(0,      (int)floorf(sx - (float)f) + 1);
            int jxhi = min(W0 - 1, (int)floorf(sx + (float)f));
            float wyTot = 0.f, wxTot = 0.f;
            for (int j = jylo; j <= jyhi; j++) wyTot += 1.f - fabsf(sy - (float)j) * invf;
            for (int j = jxlo; j <= jxhi; j++) wxTot += 1.f - fabsf(sx - (float)j) * invf;
            const float* cc = coords + tt * HW0;
            float acc = 0.f;
            for (int jy = jylo; jy <= jyhi; jy++) {
                float wy = 1.f - fabsf(sy - (float)jy) * invf;
                float ra = 0.f;
                for (int jx = jxlo; jx <= jxhi; jx++)
                    ra += (1.f - fabsf(sx - (float)jx) * invf) * cc[jy * W0 + jx];
                acc += wy * ra;
            }
            c = acc / (wyTot * wxTot) * invf;
        }
        sh_c[side][tt] = c;
    }

    // --- f1 vector for THIS WARP's side: 4x LDG.32, each one full line
    int sideW = w >> 2;         // warps 0-3 -> side 0, 4-7 -> side 1
    const float* f1p = g_f1 + loff + (2 * q + sideW) * D128;
    float a0 = f1p[lane];
    float a1 = f1p[lane + 32];
    float a2 = f1p[lane + 64];
    float a3 = f1p[lane + 96];
    ull A01 = pack2(a0, a1);
    ull A23 = pack2(a2, a3);

    __syncthreads();

    float cx = sh_c[side][0], cy = sh_c[side][1];
    int ix = (int)floorf(cx);
    int iy = (int)floorf(cy);

    // --- precompute clamped tap base offsets (float units); pad 100..127
    {
        int ty = tt / 10, tx = tt - ty * 10;
        int gy = min(max(iy + ty - 4, 0), Hl - 1);
        int gx = min(max(ix + tx - 4, 0), Wl - 1);
        sh_addr[side][tt] = (tt < 100) ? (gy * Wl + gx) * D128 : 0;
    }
    __syncthreads();

    const float* f2base = g_f2 + loff;
    int ww = w & 3;

    // --- 100 dots per side: 25 passes, one position per warp per pass
#pragma unroll 5
    for (int j = 0; j < 25; j++) {
        int pos = j * 4 + ww;   // 0..99
        const float* qp = f2base + sh_addr[sideW][pos];
        float q0 = qp[lane];
        float q1 = qp[lane + 32];
        float q2 = qp[lane + 64];
        float q3 = qp[lane + 96];
        ull acc = 0ULL;
        fma2(acc, A01, pack2(q0, q1));
        fma2(acc, A23, pack2(q2, q3));
        float2 fr; memcpy(&fr, &acc, 8);
        float s = fr.x + fr.y;
        s += __shfl_xor_sync(0xffffffffu, s, 1);
        s += __shfl_xor_sync(0xffffffffu, s, 2);
        s += __shfl_xor_sync(0xffffffffu, s, 4);
        s += __shfl_xor_sync(0xffffffffu, s, 8);
        s += __shfl_xor_sync(0xffffffffu, s, 16);
        if (lane == 0) sh_dot[sideW][pos] = s;
    }
    __syncthreads();

    // --- bilinear combine: t<162 -> (k = t/2, sd = t&1); pairwise 8B stores
    if (t < 162) {
        int k  = t >> 1;
        int sd = t & 1;
        float cx2 = sh_c[sd][0], cy2 = sh_c[sd][1];
        int ix2 = (int)floorf(cx2);
        int iy2 = (int)floorf(cy2);
        int dxi = k / 9, dyi = k - dxi * 9;
        float xq = fminf(fmaxf(cx2 + (float)(dxi - 4), 0.f), (float)(Wl - 1));
        float yq = fminf(fmaxf(cy2 + (float)(dyi - 4), 0.f), (float)(Hl - 1));
        float x0f = floorf(xq), y0f = floorf(yq);
        float wx1 = xq - x0f,  wy1 = yq - y0f;
        float wx0 = 1.f - wx1, wy0 = 1.f - wy1;
        int t0x = min(max((int)x0f - ix2 + 4, 0), 9), t1x = min(t0x + 1, 9);
        int t0y = min(max((int)y0f - iy2 + 4, 0), 9), t1y = min(t0y + 1, 9);
        float v = wy0 * (wx0 * sh_dot[sd][t0y * 10 + t0x] + wx1 * sh_dot[sd][t0y * 10 + t1x])
                + wy1 * (wx0 * sh_dot[sd][t1y * 10 + t0x] + wx1 * sh_dot[sd][t1y * 10 + t1x]);
        out[ooff + k * (Hl * Wl) + 2 * q + sd] = v * 0.08838834764831845f;  // 1/sqrt(128)
    }
}

// ---------------------------------------------------------------------------
extern "C" void kernel_launch(void* const* d_in, const int* in_sizes, int n_in,
                              void* d_out, int out_size) {
    const float* f1     = (const float*)d_in[0];
    const float* f2     = (const float*)d_in[1];
    const float* coords = (const float*)d_in[2];
    float* out = (float*)d_out;

    build_kernel<<<dim3(96, 1, 2), 512>>>(f1, f2);
    corr_kernel<<<4144, 256>>>(coords, out);
}

// round 10
// speedup vs baseline: 1.4689x; 1.4689x over previous
#include <cuda_runtime.h>
#include <cuda_fp16.h>
#include <string.h>

#define D128 128
#define H0 64
#define W0 96
#define HW0 (H0 * W0)   // 6144

// f1: fp32 pyramid (read by corr). f2: fp16 pyramid only.
// Level offsets (elements): L0 0, L1 786432, L2 983040, L3 1032192.
__device__ __align__(16) float  g_f1[1044480];
__device__ __align__(16) __half g_f2h[1044480];

typedef unsigned long long ull;

__device__ __forceinline__ void fma2(ull& d, ull a, ull b) {
    asm("fma.rn.f32x2 %0, %1, %2, %3;" : "=l"(d) : "l"(a), "l"(b), "l"(d));
}
__device__ __forceinline__ ulonglong2 asu2(float4 v) {
    ulonglong2 r; memcpy(&r, &v, 16); return r;
}

// dot of 8 halves (uint4) with 8 fp32 (two float4), fp32 accumulate
__device__ __forceinline__ float dot8(uint4 r, float4 a, float4 b) {
    __half2* h = (__half2*)&r;
    float2 f0 = __half22float2(h[0]);
    float2 f1 = __half22float2(h[1]);
    float2 f2 = __half22float2(h[2]);
    float2 f3 = __half22float2(h[3]);
    float s = a.x * f0.x + a.y * f0.y;
    s += a.z * f1.x + a.w * f1.y;
    s += b.x * f2.x + b.y * f2.y;
    s += b.z * f3.x + b.w * f3.y;
    return s;
}

// ---------------------------------------------------------------------------
// Kernel 1: fused transpose + full pyramid build. One block per 8x8 pixel
// tile per map, 512 threads. map 0 -> fp32 g_f1; map 1 -> fp16 g_f2h only.
// ---------------------------------------------------------------------------
__global__ __launch_bounds__(512) void build_kernel(const float* __restrict__ f1,
                                                    const float* __restrict__ f2) {
    __shared__ float s0[8][8][128];   // 32KB
    __shared__ float s1[4][4][128];   // 8KB
    __shared__ float s2[2][2][128];   // 2KB
    int map = blockIdx.z;
    const float* in = map ? f2 : f1;
    int tx0 = (blockIdx.x % 12) * 8;
    int ty0 = (blockIdx.x / 12) * 8;
    int t = threadIdx.x;

    {
        int d = t >> 2;
        int sl = t & 3;
        const float* src = in + d * HW0 + ty0 * W0 + tx0;
        float4 v00 = *(const float4*)(src + (2 * sl) * W0);
        float4 v01 = *(const float4*)(src + (2 * sl) * W0 + 4);
        float4 v10 = *(const float4*)(src + (2 * sl + 1) * W0);
        float4 v11 = *(const float4*)(src + (2 * sl + 1) * W0 + 4);
        int y0 = 2 * sl, y1 = 2 * sl + 1;
        s0[y0][0][d] = v00.x; s0[y0][1][d] = v00.y; s0[y0][2][d] = v00.z; s0[y0][3][d] = v00.w;
        s0[y0][4][d] = v01.x; s0[y0][5][d] = v01.y; s0[y0][6][d] = v01.z; s0[y0][7][d] = v01.w;
        s0[y1][0][d] = v10.x; s0[y1][1][d] = v10.y; s0[y1][2][d] = v10.z; s0[y1][3][d] = v10.w;
        s0[y1][4][d] = v11.x; s0[y1][5][d] = v11.y; s0[y1][6][d] = v11.z; s0[y1][7][d] = v11.w;
    }
    __syncthreads();

    // write transposed L0: 2048 float4-sized chunks, 4 per thread
#pragma unroll
    for (int i = 0; i < 4; i++) {
        int idx = i * 512 + t;
        int c4 = idx & 31;
        int px = idx >> 5;
        int y = px >> 3, x = px & 7;
        float4 w = *(float4*)&s0[y][x][c4 * 4];
        int gp = (ty0 + y) * W0 + tx0 + x;
        if (map == 0) {
            *(float4*)(g_f1 + gp * D128 + c4 * 4) = w;
        } else {
            __half2 h0 = __floats2half2_rn(w.x, w.y);
            __half2 h1 = __floats2half2_rn(w.z, w.w);
            uint2 pk = make_uint2(*(unsigned*)&h0, *(unsigned*)&h1);
            *(uint2*)(g_f2h + gp * D128 + c4 * 4) = pk;
        }
    }

    // L1: 16 px x 128 ch
#pragma unroll
    for (int i = 0; i < 4; i++) {
        int idx = i * 512 + t;
        int c = idx & 127;
        int px = idx >> 7;
        int y = px >> 2, x = px & 3;
        float r = 0.25f * (s0[2*y][2*x][c] + s0[2*y][2*x+1][c]
                         + s0[2*y+1][2*x][c] + s0[2*y+1][2*x+1][c]);
        s1[y][x][c] = r;
        int gp = (ty0 / 2 + y) * 48 + tx0 / 2 + x;
        if (map == 0) g_f1[786432 + gp * D128 + c] = r;
        else          g_f2h[786432 + gp * D128 + c] = __float2half(r);
    }
    __syncthreads();

    // L2: 4 px x 128 ch
    {
        int c = t & 127;
        int px = t >> 7;
        int y = px >> 1, x = px & 1;
        float r = 0.25f * (s1[2*y][2*x][c] + s1[2*y][2*x+1][c]
                         + s1[2*y+1][2*x][c] + s1[2*y+1][2*x+1][c]);
        s2[y][x][c] = r;
        int gp = (ty0 / 4 + y) * 24 + tx0 / 4 + x;
        if (map == 0) g_f1[983040 + gp * D128 + c] = r;
        else          g_f2h[983040 + gp * D128 + c] = __float2half(r);
    }
    __syncthreads();

    // L3: 1 px x 128 ch
    if (t < 128) {
        float r = 0.25f * (s2[0][0][t] + s2[0][1][t] + s2[1][0][t] + s2[1][1][t]);
        int gp = (ty0 / 8) * 12 + tx0 / 8;
        if (map == 0) g_f1[1032192 + gp * D128 + t] = r;
        else          g_f2h[1032192 + gp * D128 + t] = __float2half(r);
    }
}

// ---------------------------------------------------------------------------
// Kernel 2: fused correlation lookup (R6 structure). 256 threads per pixel
// PAIR. Dot phase: f2 read as fp16 (2 LDG.128 per position per 8-lane group
// -> half the L1 wavefronts of fp32), fp32 f1 + fp32 accumulation.
// ---------------------------------------------------------------------------
__global__ __launch_bounds__(256) void corr_kernel(const float* __restrict__ coords,
                                                   float* __restrict__ out) {
    int gq = (blockIdx.x % 148) * 28 + blockIdx.x / 148;
    if (gq >= 4080) return;

    int lvl, q;
    if (gq < 3072)      { lvl = 0; q = gq; }
    else if (gq < 3840) { lvl = 1; q = gq - 3072; }
    else if (gq < 4032) { lvl = 2; q = gq - 3840; }
    else                { lvl = 3; q = gq - 4032; }

    int loff, ooff;
    switch (lvl) {
        case 0:  loff = 0;       ooff = 0;      break;
        case 1:  loff = 786432;  ooff = 497664; break;
        case 2:  loff = 983040;  ooff = 622080; break;
        default: loff = 1032192; ooff = 653184; break;
    }
    const int Hl = H0 >> lvl, Wl = W0 >> lvl;

    int t    = threadIdx.x;
    int side = t >> 7;
    int tt   = t & 127;
    int p    = 2 * q + side;
    int py = p / Wl, px = p - py * Wl;

    __shared__ float sh_c[2][2];
    __shared__ int   sh_addr[2][128];
    __shared__ float sh_dot[2][112];

    int w    = tt >> 5;
    int lane = tt & 31;
    int sub  = lane & 7;
    int quad = lane >> 3;

    // --- coords at this level (jax.image.resize linear antialias semantics)
    if (tt < 2) {
        float c;
        if (lvl == 0) {
            c = coords[tt * HW0 + p];
        } else {
            int   f    = 1 << lvl;
            float invf = 1.0f / (float)f;
            float sy = ((float)py + 0.5f) * (float)f - 0.5f;
            float sx = ((float)px + 0.5f) * (float)f - 0.5f;
            int jylo = max(0,      (int)floorf(sy - (float)f) + 1);
            int jyhi = min(H0 - 1, (int)floorf(sy + (float)f));
            int jxlo = max(0,      (int)floorf(sx - (float)f) + 1);
            int jxhi = min(W0 - 1, (int)floorf(sx + (float)f));
            float wyTot = 0.f, wxTot = 0.f;
            for (int j = jylo; j <= jyhi; j++) wyTot += 1.f - fabsf(sy - (float)j) * invf;
            for (int j = jxlo; j <= jxhi; j++) wxTot += 1.f - fabsf(sx - (float)j) * invf;
            const float* cc = coords + tt * HW0;
            float acc = 0.f;
            for (int jy = jylo; jy <= jyhi; jy++) {
                float wy = 1.f - fabsf(sy - (float)jy) * invf;
                float ra = 0.f;
                for (int jx = jxlo; jx <= jxhi; jx++)
                    ra += (1.f - fabsf(sx - (float)jx) * invf) * cc[jy * W0 + jx];
                acc += wy * ra;
            }
            c = acc / (wyTot * wxTot) * invf;
        }
        sh_c[side][tt] = c;
    }

    // --- f1 fp32 chunks for this lane (chs 8*sub..8*sub+7 and 64+8*sub..)
    const float4* f1v = (const float4*)(g_f1 + loff + p * D128);
    float4 a0 = f1v[2 * sub];
    float4 a1 = f1v[2 * sub + 1];
    float4 a2 = f1v[16 + 2 * sub];
    float4 a3 = f1v[17 + 2 * sub];

    __syncthreads();

    float cx = sh_c[side][0], cy = sh_c[side][1];
    int ix = (int)floorf(cx);
    int iy = (int)floorf(cy);

    // --- precompute clamped tap base addresses (uint4 units); pad 100..127
    {
        int ty = tt / 10, tx = tt - ty * 10;
        int gy = min(max(iy + ty - 4, 0), Hl - 1);
        int gx = min(max(ix + tx - 4, 0), Wl - 1);
        sh_addr[side][tt] = (tt < 100) ? (gy * Wl + gx) * 16 : 0;
    }
    __syncthreads();

    const uint4* f2base = (const uint4*)(g_f2h + loff);  // 16B = 8 halves

    // --- 100 corner dots per side: 7 passes x (4 warps x 4 positions)
#pragma unroll
    for (int j = 0; j < 7; j++) {
        int pos = j * 16 + w * 4 + quad;     // 0..111 (padded addrs)
        const uint4* qv = f2base + sh_addr[side][pos];
        uint4 r0 = qv[sub];
        uint4 r1 = qv[8 + sub];
        float s = dot8(r0, a0, a1) + dot8(r1, a2, a3);
        s += __shfl_xor_sync(0xffffffffu, s, 1);
        s += __shfl_xor_sync(0xffffffffu, s, 2);
        s += __shfl_xor_sync(0xffffffffu, s, 4);
        if (sub == 0 && pos < 100) sh_dot[side][pos] = s;
    }
    __syncthreads();

    // --- bilinear combine: t<162 -> (k = t/2, sd = t&1); pairwise 8B stores
    if (t < 162) {
        int k  = t >> 1;
        int sd = t & 1;
        float cx2 = sh_c[sd][0], cy2 = sh_c[sd][1];
        int ix2 = (int)floorf(cx2);
        int iy2 = (int)floorf(cy2);
        int dxi = k / 9, dyi = k - dxi * 9;
        float xq = fminf(fmaxf(cx2 + (float)(dxi - 4), 0.f), (float)(Wl - 1));
        float yq = fminf(fmaxf(cy2 + (float)(dyi - 4), 0.f), (float)(Hl - 1));
        float x0f = floorf(xq), y0f = floorf(yq);
        float wx1 = xq - x0f,  wy1 = yq - y0f;
        float wx0 = 1.f - wx1, wy0 = 1.f - wy1;
        int t0x = min(max((int)x0f - ix2 + 4, 0), 9), t1x = min(t0x + 1, 9);
        int t0y = min(max((int)y0f - iy2 + 4, 0), 9), t1y = min(t0y + 1, 9);
        float v = wy0 * (wx0 * sh_dot[sd][t0y * 10 + t0x] + wx1 * sh_dot[sd][t0y * 10 + t1x])
                + wy1 * (wx0 * sh_dot[sd][t1y * 10 + t0x] + wx1 * sh_dot[sd][t1y * 10 + t1x]);
        out[ooff + k * (Hl * Wl) + 2 * q + sd] = v * 0.08838834764831845f;  // 1/sqrt(128)
    }
}

// ---------------------------------------------------------------------------
extern "C" void kernel_launch(void* const* d_in, const int* in_sizes, int n_in,
                              void* d_out, int out_size) {
    const float* f1     = (const float*)d_in[0];
    const float* f2     = (const float*)d_in[1];
    const float* coords = (const float*)d_in[2];
    float* out = (float*)d_out;

    build_kernel<<<dim3(96, 1, 2), 512>>>(f1, f2);
    corr_kernel<<<4144, 256>>>(coords, out);
}

// round 11
// speedup vs baseline: 1.8961x; 1.2908x over previous
#include <cuda_runtime.h>
#include <cuda_fp16.h>
#include <string.h>

#define D128 128
#define H0 64
#define W0 96
#define HW0 (H0 * W0)   // 6144

// f1: fp32 pyramid. f2: fp16 pyramid. Offsets: L0 0, L1 786432, L2 983040, L3 1032192.
__device__ __align__(16) float  g_f1[1044480];
__device__ __align__(16) __half g_f2h[1044480];

typedef unsigned long long ull;

__device__ __forceinline__ void fma2(ull& d, ull a, ull b) {
    asm("fma.rn.f32x2 %0, %1, %2, %3;" : "=l"(d) : "l"(a), "l"(b), "l"(d));
}
__device__ __forceinline__ ull pk2(float2 v) {
    ull r; memcpy(&r, &v, 8); return r;
}

// ---------------------------------------------------------------------------
// Kernel 1: fused transpose + full pyramid build. One block per 8x8 pixel
// tile per map, 512 threads. map 0 -> fp32 g_f1; map 1 -> fp16 g_f2h.
// ---------------------------------------------------------------------------
__global__ __launch_bounds__(512) void build_kernel(const float* __restrict__ f1,
                                                    const float* __restrict__ f2) {
    __shared__ float s0[8][8][128];
    __shared__ float s1[4][4][128];
    __shared__ float s2[2][2][128];
    int map = blockIdx.z;
    const float* in = map ? f2 : f1;
    int tx0 = (blockIdx.x % 12) * 8;
    int ty0 = (blockIdx.x / 12) * 8;
    int t = threadIdx.x;

    {
        int d = t >> 2;
        int sl = t & 3;
        const float* src = in + d * HW0 + ty0 * W0 + tx0;
        float4 v00 = *(const float4*)(src + (2 * sl) * W0);
        float4 v01 = *(const float4*)(src + (2 * sl) * W0 + 4);
        float4 v10 = *(const float4*)(src + (2 * sl + 1) * W0);
        float4 v11 = *(const float4*)(src + (2 * sl + 1) * W0 + 4);
        int y0 = 2 * sl, y1 = 2 * sl + 1;
        s0[y0][0][d] = v00.x; s0[y0][1][d] = v00.y; s0[y0][2][d] = v00.z; s0[y0][3][d] = v00.w;
        s0[y0][4][d] = v01.x; s0[y0][5][d] = v01.y; s0[y0][6][d] = v01.z; s0[y0][7][d] = v01.w;
        s0[y1][0][d] = v10.x; s0[y1][1][d] = v10.y; s0[y1][2][d] = v10.z; s0[y1][3][d] = v10.w;
        s0[y1][4][d] = v11.x; s0[y1][5][d] = v11.y; s0[y1][6][d] = v11.z; s0[y1][7][d] = v11.w;
    }
    __syncthreads();

#pragma unroll
    for (int i = 0; i < 4; i++) {
        int idx = i * 512 + t;
        int c4 = idx & 31;
        int px = idx >> 5;
        int y = px >> 3, x = px & 7;
        float4 w = *(float4*)&s0[y][x][c4 * 4];
        int gp = (ty0 + y) * W0 + tx0 + x;
        if (map == 0) {
            *(float4*)(g_f1 + gp * D128 + c4 * 4) = w;
        } else {
            __half2 h0 = __floats2half2_rn(w.x, w.y);
            __half2 h1 = __floats2half2_rn(w.z, w.w);
            uint2 pk = make_uint2(*(unsigned*)&h0, *(unsigned*)&h1);
            *(uint2*)(g_f2h + gp * D128 + c4 * 4) = pk;
        }
    }

#pragma unroll
    for (int i = 0; i < 4; i++) {
        int idx = i * 512 + t;
        int c = idx & 127;
        int px = idx >> 7;
        int y = px >> 2, x = px & 3;
        float r = 0.25f * (s0[2*y][2*x][c] + s0[2*y][2*x+1][c]
                         + s0[2*y+1][2*x][c] + s0[2*y+1][2*x+1][c]);
        s1[y][x][c] = r;
        int gp = (ty0 / 2 + y) * 48 + tx0 / 2 + x;
        if (map == 0) g_f1[786432 + gp * D128 + c] = r;
        else          g_f2h[786432 + gp * D128 + c] = __float2half(r);
    }
    __syncthreads();

    {
        int c = t & 127;
        int px = t >> 7;
        int y = px >> 1, x = px & 1;
        float r = 0.25f * (s1[2*y][2*x][c] + s1[2*y][2*x+1][c]
                         + s1[2*y+1][2*x][c] + s1[2*y+1][2*x+1][c]);
        s2[y][x][c] = r;
        int gp = (ty0 / 4 + y) * 24 + tx0 / 4 + x;
        if (map == 0) g_f1[983040 + gp * D128 + c] = r;
        else          g_f2h[983040 + gp * D128 + c] = __float2half(r);
    }
    __syncthreads();

    if (t < 128) {
        float r = 0.25f * (s2[0][0][t] + s2[0][1][t] + s2[1][0][t] + s2[1][1][t]);
        int gp = (ty0 / 8) * 12 + tx0 / 8;
        if (map == 0) g_f1[1032192 + gp * D128 + t] = r;
        else          g_f2h[1032192 + gp * D128 + t] = __float2half(r);
    }
}

// ---------------------------------------------------------------------------
// Kernel 2: fused correlation. 512 threads handle FOUR consecutive pixels
// (side = t>>7). Coords resize is warp-parallel (lanes tile the tap grid).
// Dot phase: fp16 f2 loads, cvt + packed fma.rn.f32x2, fp32 accumulate.
// ---------------------------------------------------------------------------
__global__ __launch_bounds__(512) void corr_kernel(const float* __restrict__ coords,
                                                   float* __restrict__ out) {
    int g4 = (blockIdx.x % 148) * 14 + blockIdx.x / 148;
    if (g4 >= 2040) return;

    int lvl, q;
    if (g4 < 1536)      { lvl = 0; q = g4; }
    else if (g4 < 1920) { lvl = 1; q = g4 - 1536; }
    else if (g4 < 2016) { lvl = 2; q = g4 - 1920; }
    else                { lvl = 3; q = g4 - 2016; }

    int loff, ooff;
    switch (lvl) {
        case 0:  loff = 0;       ooff = 0;      break;
        case 1:  loff = 786432;  ooff = 497664; break;
        case 2:  loff = 983040;  ooff = 622080; break;
        default: loff = 1032192; ooff = 653184; break;
    }
    const int Hl = H0 >> lvl, Wl = W0 >> lvl;

    int t    = threadIdx.x;
    int side = t >> 7;          // pixel 0..3 of the quad
    int tt   = t & 127;
    int p    = 4 * q + side;
    int py = p / Wl, px = p - py * Wl;

    __shared__ float sh_c[4][2];
    __shared__ int   sh_addr[4][128];
    __shared__ float sh_dot[4][112];

    int w2   = tt >> 5;
    int lane = tt & 31;
    int sub  = lane & 7;
    int quad = lane >> 3;

    // --- f1 fp32 chunks for this lane; issue LDGs before coords work
    const float4* f1v = (const float4*)(g_f1 + loff + p * D128);
    float4 a0 = f1v[2 * sub];
    float4 a1 = f1v[2 * sub + 1];
    float4 a2 = f1v[16 + 2 * sub];
    float4 a3 = f1v[17 + 2 * sub];

    // --- coords: one warp per side, lanes tile the (jy, jx) tap grid.
    // jax.image.resize linear antialias: triangle kernel scale f=2^lvl,
    // normalized by sum of in-range weights (= wyTot*wxTot), then /f.
    if (tt < 32) {
        if (lvl == 0) {
            if (lane < 2) sh_c[side][lane] = coords[lane * HW0 + p];
        } else {
            int   f    = 1 << lvl;
            float invf = 1.0f / (float)f;
            float sy = ((float)py + 0.5f) * (float)f - 0.5f;
            float sx = ((float)px + 0.5f) * (float)f - 0.5f;
            int jylo = max(0,      (int)floorf(sy - (float)f) + 1);
            int jyhi = min(H0 - 1, (int)floorf(sy + (float)f));
            int jxlo = max(0,      (int)floorf(sx - (float)f) + 1);
            int jxhi = min(W0 - 1, (int)floorf(sx + (float)f));
            int jx = jxlo + (lane & 15);
            bool okx = (jx <= jxhi);
            float wx = okx ? (1.f - fabsf(sx - (float)jx) * invf) : 0.f;
            float acc0 = 0.f, acc1 = 0.f, ws = 0.f;
            for (int jy = jylo + (lane >> 4); jy <= jyhi; jy += 2) {
                float wy = 1.f - fabsf(sy - (float)jy) * invf;
                float ww = wy * wx;
                if (okx) {
                    acc0 += ww * coords[jy * W0 + jx];
                    acc1 += ww * coords[HW0 + jy * W0 + jx];
                    ws   += ww;
                }
            }
#pragma unroll
            for (int m = 16; m; m >>= 1) {
                acc0 += __shfl_xor_sync(0xffffffffu, acc0, m);
                acc1 += __shfl_xor_sync(0xffffffffu, acc1, m);
                ws   += __shfl_xor_sync(0xffffffffu, ws,   m);
            }
            if (lane == 0) {
                float inv = invf / ws;
                sh_c[side][0] = acc0 * inv;
                sh_c[side][1] = acc1 * inv;
            }
        }
    }
    __syncthreads();

    float cx = sh_c[side][0], cy = sh_c[side][1];
    int ix = (int)floorf(cx);
    int iy = (int)floorf(cy);

    // --- precompute clamped tap base addresses (uint4 units); pad 100..127
    {
        int ty = tt / 10, tx = tt - ty * 10;
        int gy = min(max(iy + ty - 4, 0), Hl - 1);
        int gx = min(max(ix + tx - 4, 0), Wl - 1);
        sh_addr[side][tt] = (tt < 100) ? (gy * Wl + gx) * 16 : 0;
    }
    __syncthreads();

    // pack f1 pairs for fma2 (ch pairs match half2 lanes of the fp16 loads)
    ull A0, A1, A2, A3, A4, A5, A6, A7;
    { ulonglong2 u; memcpy(&u, &a0, 16); A0 = u.x; A1 = u.y; }
    { ulonglong2 u; memcpy(&u, &a1, 16); A2 = u.x; A3 = u.y; }
    { ulonglong2 u; memcpy(&u, &a2, 16); A4 = u.x; A5 = u.y; }
    { ulonglong2 u; memcpy(&u, &a3, 16); A6 = u.x; A7 = u.y; }

    const uint4* f2base = (const uint4*)(g_f2h + loff);

    // --- 100 corner dots per side: 7 passes x (4 warps x 4 positions)
#pragma unroll
    for (int j = 0; j < 7; j++) {
        int pos = j * 16 + w2 * 4 + quad;     // 0..111 (padded addrs)
        const uint4* qv = f2base + sh_addr[side][pos];
        uint4 r0 = qv[sub];
        uint4 r1 = qv[8 + sub];
        const __half2* h0 = (const __half2*)&r0;
        const __half2* h1 = (const __half2*)&r1;
        ull acc = 0ULL;
        fma2(acc, A0, pk2(__half22float2(h0[0])));
        fma2(acc, A1, pk2(__half22float2(h0[1])));
        fma2(acc, A2, pk2(__half22float2(h0[2])));
        fma2(acc, A3, pk2(__half22float2(h0[3])));
        fma2(acc, A4, pk2(__half22float2(h1[0])));
        fma2(acc, A5, pk2(__half22float2(h1[1])));
        fma2(acc, A6, pk2(__half22float2(h1[2])));
        fma2(acc, A7, pk2(__half22float2(h1[3])));
        float2 fr; memcpy(&fr, &acc, 8);
        float s = fr.x + fr.y;
        s += __shfl_xor_sync(0xffffffffu, s, 1);
        s += __shfl_xor_sync(0xffffffffu, s, 2);
        s += __shfl_xor_sync(0xffffffffu, s, 4);
        if (sub == 0 && pos < 100) sh_dot[side][pos] = s;
    }
    __syncthreads();

    // --- bilinear combine: t<324 -> (k = t/4, sd = t&3); 16B-contiguous
    // stores per output line.
    if (t < 324) {
        int k  = t >> 2;
        int sd = t & 3;
        float cx2 = sh_c[sd][0], cy2 = sh_c[sd][1];
        int ix2 = (int)floorf(cx2);
        int iy2 = (int)floorf(cy2);
        int dxi = k / 9, dyi = k - dxi * 9;
        float xq = fminf(fmaxf(cx2 + (float)(dxi - 4), 0.f), (float)(Wl - 1));
        float yq = fminf(fmaxf(cy2 + (float)(dyi - 4), 0.f), (float)(Hl - 1));
        float x0f = floorf(xq), y0f = floorf(yq);
        float wx1 = xq - x0f,  wy1 = yq - y0f;
        float wx0 = 1.f - wx1, wy0 = 1.f - wy1;
        int t0x = min(max((int)x0f - ix2 + 4, 0), 9), t1x = min(t0x + 1, 9);
        int t0y = min(max((int)y0f - iy2 + 4, 0), 9), t1y = min(t0y + 1, 9);
        float v = wy0 * (wx0 * sh_dot[sd][t0y * 10 + t0x] + wx1 * sh_dot[sd][t0y * 10 + t1x])
                + wy1 * (wx0 * sh_dot[sd][t1y * 10 + t0x] + wx1 * sh_dot[sd][t1y * 10 + t1x]);
        out[ooff + k * (Hl * Wl) + 4 * q + sd] = v * 0.08838834764831845f;  // 1/sqrt(128)
    }
}

// ---------------------------------------------------------------------------
extern "C" void kernel_launch(void* const* d_in, const int* in_sizes, int n_in,
                              void* d_out, int out_size) {
    const float* f1     = (const float*)d_in[0];
    const float* f2     = (const float*)d_in[1];
    const float* coords = (const float*)d_in[2];
    float* out = (float*)d_out;

    build_kernel<<<dim3(96, 1, 2), 512>>>(f1, f2);
    // 148 * 14 = 2072 blocks cover 2040 pixel-quads, SM-contiguous mapping
    corr_kernel<<<2072, 512>>>(coords, out);
}

// round 12
// speedup vs baseline: 2.2018x; 1.1612x over previous
#include <cuda_runtime.h>
#include <cuda_fp16.h>
#include <string.h>

#define D128 128
#define H0 64
#define W0 96
#define HW0 (H0 * W0)   // 6144

// f1: fp32 pyramid. f2: fp16 pyramid. Offsets: L0 0, L1 786432, L2 983040, L3 1032192.
__device__ __align__(16) float  g_f1[1044480];
__device__ __align__(16) __half g_f2h[1044480];

typedef unsigned long long ull;

__device__ __forceinline__ void fma2(ull& d, ull a, ull b) {
    asm("fma.rn.f32x2 %0, %1, %2, %3;" : "=l"(d) : "l"(a), "l"(b), "l"(d));
}
__device__ __forceinline__ ull pk2(float2 v) {
    ull r; memcpy(&r, &v, 8); return r;
}

// ---------------------------------------------------------------------------
// Kernel 1: fused transpose + pyramid build, split into 64-channel slices
// for 4x the blocks (384 total). grid (96, 2, 2): x = 8x8 tile, y = channel
// slice, z = map. map 0 -> fp32 g_f1; map 1 -> fp16 g_f2h.
// ---------------------------------------------------------------------------
__global__ __launch_bounds__(512) void build_kernel(const float* __restrict__ f1,
                                                    const float* __restrict__ f2) {
    __shared__ float s0[8][8][64];   // 16KB
    __shared__ float s1[4][4][64];   // 4KB
    __shared__ float s2[2][2][64];   // 1KB
    int map = blockIdx.z;
    int cB  = blockIdx.y * 64;
    const float* in = map ? f2 : f1;
    int tx0 = (blockIdx.x % 12) * 8;
    int ty0 = (blockIdx.x / 12) * 8;
    int t = threadIdx.x;

    // load: local channel d = t>>3, row sl = t&7; 8 px = 2 float4
    {
        int d  = t >> 3;
        int sl = t & 7;
        const float* src = in + (cB + d) * HW0 + (ty0 + sl) * W0 + tx0;
        float4 v0 = *(const float4*)(src);
        float4 v1 = *(const float4*)(src + 4);
        s0[sl][0][d] = v0.x; s0[sl][1][d] = v0.y; s0[sl][2][d] = v0.z; s0[sl][3][d] = v0.w;
        s0[sl][4][d] = v1.x; s0[sl][5][d] = v1.y; s0[sl][6][d] = v1.z; s0[sl][7][d] = v1.w;
    }
    __syncthreads();

    // transposed L0: 64 px x 16 float4 = 1024 chunks, 2/thread
#pragma unroll
    for (int i = 0; i < 2; i++) {
        int idx = i * 512 + t;
        int c4 = idx & 15;
        int px = idx >> 4;
        int y = px >> 3, x = px & 7;
        float4 w = *(float4*)&s0[y][x][c4 * 4];
        int go = ((ty0 + y) * W0 + tx0 + x) * D128 + cB + c4 * 4;
        if (map == 0) {
            *(float4*)(g_f1 + go) = w;
        } else {
            __half2 h0 = __floats2half2_rn(w.x, w.y);
            __half2 h1 = __floats2half2_rn(w.z, w.w);
            uint2 pk = make_uint2(*(unsigned*)&h0, *(unsigned*)&h1);
            *(uint2*)(g_f2h + go) = pk;
        }
    }

    // L1: 16 px x 64 ch = 1024, 2/thread
#pragma unroll
    for (int i = 0; i < 2; i++) {
        int idx = i * 512 + t;
        int c = idx & 63;
        int px = idx >> 6;
        int y = px >> 2, x = px & 3;
        float r = 0.25f * (s0[2*y][2*x][c] + s0[2*y][2*x+1][c]
                         + s0[2*y+1][2*x][c] + s0[2*y+1][2*x+1][c]);
        s1[y][x][c] = r;
        int go = 786432 + ((ty0 / 2 + y) * 48 + tx0 / 2 + x) * D128 + cB + c;
        if (map == 0) g_f1[go] = r;
        else          g_f2h[go] = __float2half(r);
    }
    __syncthreads();

    // L2: 4 px x 64 ch = 256
    if (t < 256) {
        int c = t & 63;
        int px = t >> 6;
        int y = px >> 1, x = px & 1;
        float r = 0.25f * (s1[2*y][2*x][c] + s1[2*y][2*x+1][c]
                         + s1[2*y+1][2*x][c] + s1[2*y+1][2*x+1][c]);
        s2[y][x][c] = r;
        int go = 983040 + ((ty0 / 4 + y) * 24 + tx0 / 4 + x) * D128 + cB + c;
        if (map == 0) g_f1[go] = r;
        else          g_f2h[go] = __float2half(r);
    }
    __syncthreads();

    // L3: 1 px x 64 ch
    if (t < 64) {
        float r = 0.25f * (s2[0][0][t] + s2[0][1][t] + s2[1][0][t] + s2[1][1][t]);
        int go = 1032192 + ((ty0 / 8) * 12 + tx0 / 8) * D128 + cB + t;
        if (map == 0) g_f1[go] = r;
        else          g_f2h[go] = __float2half(r);
    }
}

// ---------------------------------------------------------------------------
// Kernel 2: fused correlation. 512 threads handle EIGHT consecutive pixels
// (side = t>>6, 2 warps per pixel, 13 passes of 8 position-slots).
// Coords: one warp per pixel (8 parallel warps). Dot: fp16 f2 loads,
// cvt + packed fma.rn.f32x2, fp32 accumulate.
// ---------------------------------------------------------------------------
__global__ __launch_bounds__(512) void corr_kernel(const float* __restrict__ coords,
                                                   float* __restrict__ out) {
    int g8 = (blockIdx.x % 148) * 7 + blockIdx.x / 148;
    if (g8 >= 1020) return;

    int lvl, q;
    if (g8 < 768)       { lvl = 0; q = g8; }
    else if (g8 < 960)  { lvl = 1; q = g8 - 768; }
    else if (g8 < 1008) { lvl = 2; q = g8 - 960; }
    else                { lvl = 3; q = g8 - 1008; }

    int loff, ooff;
    switch (lvl) {
        case 0:  loff = 0;       ooff = 0;      break;
        case 1:  loff = 786432;  ooff = 497664; break;
        case 2:  loff = 983040;  ooff = 622080; break;
        default: loff = 1032192; ooff = 653184; break;
    }
    const int Hl = H0 >> lvl, Wl = W0 >> lvl;

    int t    = threadIdx.x;
    int side = t >> 6;          // pixel 0..7 of the octet
    int tt   = t & 63;
    int p    = 8 * q + side;

    __shared__ float sh_c[8][2];
    __shared__ int   sh_addr[8][104];
    __shared__ float sh_dot[8][104];

    int w2   = tt >> 5;         // warp-within-side 0..1
    int lane = t & 31;
    int sub  = lane & 7;
    int quad = lane >> 3;

    // --- f1 fp32 chunks for this lane; issue LDGs before coords work
    const float4* f1v = (const float4*)(g_f1 + loff + p * D128);
    float4 a0 = f1v[2 * sub];
    float4 a1 = f1v[2 * sub + 1];
    float4 a2 = f1v[16 + 2 * sub];
    float4 a3 = f1v[17 + 2 * sub];

    // --- coords: warps 0..7 each handle one pixel of the octet.
    // jax.image.resize linear antialias: triangle kernel scale f=2^lvl,
    // normalized by sum of in-range weights, then /f.
    if (t < 256) {
        int wpix = t >> 5;      // 0..7
        int pc = 8 * q + wpix;
        int pyc = pc / Wl, pxc = pc - pyc * Wl;
        if (lvl == 0) {
            if (lane < 2) sh_c[wpix][lane] = coords[lane * HW0 + pc];
        } else {
            int   f    = 1 << lvl;
            float invf = 1.0f / (float)f;
            float sy = ((float)pyc + 0.5f) * (float)f - 0.5f;
            float sx = ((float)pxc + 0.5f) * (float)f - 0.5f;
            int jylo = max(0,      (int)floorf(sy - (float)f) + 1);
            int jyhi = min(H0 - 1, (int)floorf(sy + (float)f));
            int jxlo = max(0,      (int)floorf(sx - (float)f) + 1);
            int jxhi = min(W0 - 1, (int)floorf(sx + (float)f));
            int jx = jxlo + (lane & 15);
            bool okx = (jx <= jxhi);
            float wx = okx ? (1.f - fabsf(sx - (float)jx) * invf) : 0.f;
            float acc0 = 0.f, acc1 = 0.f, ws = 0.f;
            for (int jy = jylo + (lane >> 4); jy <= jyhi; jy += 2) {
                float wy = 1.f - fabsf(sy - (float)jy) * invf;
                float ww = wy * wx;
                if (okx) {
                    acc0 += ww * coords[jy * W0 + jx];
                    acc1 += ww * coords[HW0 + jy * W0 + jx];
                    ws   += ww;
                }
            }
#pragma unroll
            for (int m = 16; m; m >>= 1) {
                acc0 += __shfl_xor_sync(0xffffffffu, acc0, m);
                acc1 += __shfl_xor_sync(0xffffffffu, acc1, m);
                ws   += __shfl_xor_sync(0xffffffffu, ws,   m);
            }
            if (lane == 0) {
                float inv = invf / ws;
                sh_c[wpix][0] = acc0 * inv;
                sh_c[wpix][1] = acc1 * inv;
            }
        }
    }
    __syncthreads();

    float cx = sh_c[side][0], cy = sh_c[side][1];
    int ix = (int)floorf(cx);
    int iy = (int)floorf(cy);

    // --- precompute clamped tap base addresses (uint4 units); pad 100..103
#pragma unroll
    for (int idx = tt; idx < 104; idx += 64) {
        int ty = idx / 10, tx = idx - ty * 10;
        int gy = min(max(iy + ty - 4, 0), Hl - 1);
        int gx = min(max(ix + tx - 4, 0), Wl - 1);
        sh_addr[side][idx] = (idx < 100) ? (gy * Wl + gx) * 16 : 0;
    }
    __syncthreads();

    // pack f1 pairs for fma2 (pairs match half2 lanes of the fp16 loads)
    ull A0, A1, A2, A3, A4, A5, A6, A7;
    { ulonglong2 u; memcpy(&u, &a0, 16); A0 = u.x; A1 = u.y; }
    { ulonglong2 u; memcpy(&u, &a1, 16); A2 = u.x; A3 = u.y; }
    { ulonglong2 u; memcpy(&u, &a2, 16); A4 = u.x; A5 = u.y; }
    { ulonglong2 u; memcpy(&u, &a3, 16); A6 = u.x; A7 = u.y; }

    const uint4* f2base = (const uint4*)(g_f2h + loff);

    // --- 100 corner dots per side: 13 passes x (2 warps x 4 positions)
#pragma unroll
    for (int j = 0; j < 13; j++) {
        int pos = j * 8 + w2 * 4 + quad;     // 0..103 (padded addrs)
        const uint4* qv = f2base + sh_addr[side][pos];
        uint4 r0 = qv[sub];
        uint4 r1 = qv[8 + sub];
        const __half2* h0 = (const __half2*)&r0;
        const __half2* h1 = (const __half2*)&r1;
        ull acc = 0ULL;
        fma2(acc, A0, pk2(__half22float2(h0[0])));
        fma2(acc, A1, pk2(__half22float2(h0[1])));
        fma2(acc, A2, pk2(__half22float2(h0[2])));
        fma2(acc, A3, pk2(__half22float2(h0[3])));
        fma2(acc, A4, pk2(__half22float2(h1[0])));
        fma2(acc, A5, pk2(__half22float2(h1[1])));
        fma2(acc, A6, pk2(__half22float2(h1[2])));
        fma2(acc, A7, pk2(__half22float2(h1[3])));
        float2 fr; memcpy(&fr, &acc, 8);
        float s = fr.x + fr.y;
        s += __shfl_xor_sync(0xffffffffu, s, 1);
        s += __shfl_xor_sync(0xffffffffu, s, 2);
        s += __shfl_xor_sync(0xffffffffu, s, 4);
        if (sub == 0 && pos < 100) sh_dot[side][pos] = s;
    }
    __syncthreads();

    // --- bilinear combine: 648 outputs (81 k x 8 px), 32B-contiguous stores
    for (int idx = t; idx < 648; idx += 512) {
        int k  = idx >> 3;
        int sd = idx & 7;
        float cx2 = sh_c[sd][0], cy2 = sh_c[sd][1];
        int ix2 = (int)floorf(cx2);
        int iy2 = (int)floorf(cy2);
        int dxi = k / 9, dyi = k - dxi * 9;
        float xq = fminf(fmaxf(cx2 + (float)(dxi - 4), 0.f), (float)(Wl - 1));
        float yq = fminf(fmaxf(cy2 + (float)(dyi - 4), 0.f), (float)(Hl - 1));
        float x0f = floorf(xq), y0f = floorf(yq);
        float wx1 = xq - x0f,  wy1 = yq - y0f;
        float wx0 = 1.f - wx1, wy0 = 1.f - wy1;
        int t0x = min(max((int)x0f - ix2 + 4, 0), 9), t1x = min(t0x + 1, 9);
        int t0y = min(max((int)y0f - iy2 + 4, 0), 9), t1y = min(t0y + 1, 9);
        float v = wy0 * (wx0 * sh_dot[sd][t0y * 10 + t0x] + wx1 * sh_dot[sd][t0y * 10 + t1x])
                + wy1 * (wx0 * sh_dot[sd][t1y * 10 + t0x] + wx1 * sh_dot[sd][t1y * 10 + t1x]);
        out[ooff + k * (Hl * Wl) + 8 * q + sd] = v * 0.08838834764831845f;  // 1/sqrt(128)
    }
}

// ---------------------------------------------------------------------------
extern "C" void kernel_launch(void* const* d_in, const int* in_sizes, int n_in,
                              void* d_out, int out_size) {
    const float* f1     = (const float*)d_in[0];
    const float* f2     = (const float*)d_in[1];
    const float* coords = (const float*)d_in[2];
    float* out = (float*)d_out;

    build_kernel<<<dim3(96, 2, 2), 512>>>(f1, f2);
    // 148 * 7 = 1036 blocks cover 1020 pixel-octets, SM-contiguous mapping
    corr_kernel<<<1036, 512>>>(coords, out);
}